// round 1
// baseline (speedup 1.0000x reference)
#include <cuda_runtime.h>
#include <math.h>

// Problem constants
#define B_   8
#define T_   2048
#define C_   1024
#define H_   64
#define NROW (B_ * T_)          // 16384
#define PAD  68                 // smem row pad (floats): 16B-aligned, conflict-free

// Scratch for projected Q, K, V (4 MB each)
__device__ float g_Q[NROW * H_];
__device__ float g_K[NROW * H_];
__device__ float g_V[NROW * H_];

// ---------------------------------------------------------------------------
// Projection: dst[M,64] = x[M,1024] @ w[1024,64] + bias
// Block: 64 rows x 64 cols, 256 threads, 4x4 register tile per thread.
// grid = (256 M-tiles, 3 {q,k,v})
// ---------------------------------------------------------------------------
__global__ __launch_bounds__(256) void proj_kernel(
    const float* __restrict__ x,
    const float* __restrict__ wq, const float* __restrict__ bq,
    const float* __restrict__ wk, const float* __restrict__ bk,
    const float* __restrict__ wv, const float* __restrict__ bv)
{
    __shared__ float Xs[64 * PAD];   // x tile, transposed: Xs[k][r]
    __shared__ float Ws[64 * PAD];   // w tile: Ws[k][c]

    const int which = blockIdx.y;
    const float* __restrict__ w    = (which == 0) ? wq : (which == 1) ? wk : wv;
    const float* __restrict__ bias = (which == 0) ? bq : (which == 1) ? bk : bv;
    float* __restrict__ dst        = (which == 0) ? g_Q : (which == 1) ? g_K : g_V;

    const int tid = threadIdx.x;
    const int tx  = tid & 15;        // col group (4 cols)
    const int ty  = tid >> 4;        // row group (4 rows)
    const int m0  = blockIdx.x * 64;

    float acc[4][4] = {};

    for (int kk = 0; kk < C_; kk += 64) {
        __syncthreads();
        // Load x tile [64 rows][64 k] transposed into Xs[k][r]
        #pragma unroll
        for (int it = 0; it < 4; ++it) {
            int v  = tid + it * 256;        // float4 unit 0..1023
            int r  = v >> 4;                // row 0..63
            int k4 = (v & 15) << 2;         // k 0,4,..,60
            float4 t = *(const float4*)(x + (size_t)(m0 + r) * C_ + kk + k4);
            Xs[(k4 + 0) * PAD + r] = t.x;
            Xs[(k4 + 1) * PAD + r] = t.y;
            Xs[(k4 + 2) * PAD + r] = t.z;
            Xs[(k4 + 3) * PAD + r] = t.w;
        }
        // Load w tile [64 k][64 c] as-is
        #pragma unroll
        for (int it = 0; it < 4; ++it) {
            int v  = tid + it * 256;
            int k  = v >> 4;
            int c4 = (v & 15) << 2;
            float4 t = *(const float4*)(w + (size_t)(kk + k) * H_ + c4);
            *(float4*)(Ws + k * PAD + c4) = t;
        }
        __syncthreads();

        #pragma unroll 8
        for (int k = 0; k < 64; ++k) {
            float4 a = *(const float4*)(Xs + k * PAD + ty * 4);
            float4 b = *(const float4*)(Ws + k * PAD + tx * 4);
            acc[0][0] += a.x * b.x; acc[0][1] += a.x * b.y; acc[0][2] += a.x * b.z; acc[0][3] += a.x * b.w;
            acc[1][0] += a.y * b.x; acc[1][1] += a.y * b.y; acc[1][2] += a.y * b.z; acc[1][3] += a.y * b.w;
            acc[2][0] += a.z * b.x; acc[2][1] += a.z * b.y; acc[2][2] += a.z * b.z; acc[2][3] += a.z * b.w;
            acc[3][0] += a.w * b.x; acc[3][1] += a.w * b.y; acc[3][2] += a.w * b.z; acc[3][3] += a.w * b.w;
        }
    }

    float4 bb = *(const float4*)(bias + tx * 4);
    #pragma unroll
    for (int i = 0; i < 4; ++i) {
        float4 o;
        o.x = acc[i][0] + bb.x;
        o.y = acc[i][1] + bb.y;
        o.z = acc[i][2] + bb.z;
        o.w = acc[i][3] + bb.w;
        *(float4*)(dst + (size_t)(m0 + ty * 4 + i) * H_ + tx * 4) = o;
    }
}

// ---------------------------------------------------------------------------
// Flash-style causal attention.
// Block handles q-tile pair (qt, 31-qt) for one batch -> uniform 33 k-tiles.
// q-tile = 64 rows, k-tile = 64 keys. 256 threads, 4x4 register tiles.
// grid = (16 pairs, 8 batches)
// ---------------------------------------------------------------------------
#define SM_TILE (64 * PAD)

__global__ __launch_bounds__(256) void attn_kernel(float* __restrict__ out)
{
    extern __shared__ float sm[];
    float* Qt = sm;                 // [h][r] transposed
    float* Kt = sm + SM_TILE;       // [h][j] transposed
    float* Vs = sm + 2 * SM_TILE;   // [j][h]
    float* Pt = sm + 3 * SM_TILE;   // [j][r] transposed

    const int b   = blockIdx.y;
    const int px  = blockIdx.x;     // pair index 0..15
    const int tid = threadIdx.x;
    const int tx  = tid & 15;
    const int ty  = tid >> 4;
    const float scale = 0.03125f;   // 1024^-0.5

    #pragma unroll 1
    for (int half = 0; half < 2; ++half) {
        const int qt = half ? (31 - px) : px;
        const int q0 = qt * 64;
        const float* __restrict__ Qg = g_Q + ((size_t)b * T_ + q0) * H_;

        __syncthreads();   // protect Qt reuse across halves
        // Load Q tile transposed: Qt[h][r]
        #pragma unroll
        for (int it = 0; it < 4; ++it) {
            int v  = tid + it * 256;
            int r  = v >> 4;
            int h4 = (v & 15) << 2;
            float4 t = *(const float4*)(Qg + r * H_ + h4);
            Qt[(h4 + 0) * PAD + r] = t.x;
            Qt[(h4 + 1) * PAD + r] = t.y;
            Qt[(h4 + 2) * PAD + r] = t.z;
            Qt[(h4 + 3) * PAD + r] = t.w;
        }

        float m[4], l[4], o[4][4];
        #pragma unroll
        for (int i = 0; i < 4; ++i) {
            m[i] = -INFINITY; l[i] = 0.f;
            o[i][0] = o[i][1] = o[i][2] = o[i][3] = 0.f;
        }

        #pragma unroll 1
        for (int kt = 0; kt <= qt; ++kt) {
            const int kb = kt * 64;
            const float* __restrict__ Kg = g_K + ((size_t)b * T_ + kb) * H_;
            const float* __restrict__ Vg = g_V + ((size_t)b * T_ + kb) * H_;

            __syncthreads();   // prev PV reads of Pt/Vs done
            // Load K tile transposed: Kt[h][j]; V tile direct: Vs[j][h]
            #pragma unroll
            for (int it = 0; it < 4; ++it) {
                int v  = tid + it * 256;
                int j  = v >> 4;
                int h4 = (v & 15) << 2;
                float4 t = *(const float4*)(Kg + j * H_ + h4);
                Kt[(h4 + 0) * PAD + j] = t.x;
                Kt[(h4 + 1) * PAD + j] = t.y;
                Kt[(h4 + 2) * PAD + j] = t.z;
                Kt[(h4 + 3) * PAD + j] = t.w;
                float4 u = *(const float4*)(Vg + j * H_ + h4);
                *(float4*)(Vs + j * PAD + h4) = u;
            }
            __syncthreads();

            // Scores: s[r][j] = sum_h Qt[h][r] * Kt[h][j]
            float s[4][4] = {};
            #pragma unroll 8
            for (int h = 0; h < 64; ++h) {
                float4 a = *(const float4*)(Qt + h * PAD + ty * 4);
                float4 k = *(const float4*)(Kt + h * PAD + tx * 4);
                s[0][0] += a.x * k.x; s[0][1] += a.x * k.y; s[0][2] += a.x * k.z; s[0][3] += a.x * k.w;
                s[1][0] += a.y * k.x; s[1][1] += a.y * k.y; s[1][2] += a.y * k.z; s[1][3] += a.y * k.w;
                s[2][0] += a.z * k.x; s[2][1] += a.z * k.y; s[2][2] += a.z * k.z; s[2][3] += a.z * k.w;
                s[3][0] += a.w * k.x; s[3][1] += a.w * k.y; s[3][2] += a.w * k.z; s[3][3] += a.w * k.w;
            }
            #pragma unroll
            for (int i = 0; i < 4; ++i)
                #pragma unroll
                for (int j = 0; j < 4; ++j)
                    s[i][j] *= scale;

            if (kt == qt) {   // diagonal tile: causal mask (block-uniform branch)
                #pragma unroll
                for (int i = 0; i < 4; ++i)
                    #pragma unroll
                    for (int j = 0; j < 4; ++j)
                        if (kb + tx * 4 + j > q0 + ty * 4 + i) s[i][j] = -INFINITY;
            }

            // Online softmax per row (row spread over 16 lanes in one warp half)
            #pragma unroll
            for (int i = 0; i < 4; ++i) {
                float rm = fmaxf(fmaxf(s[i][0], s[i][1]), fmaxf(s[i][2], s[i][3]));
                #pragma unroll
                for (int off = 8; off > 0; off >>= 1)
                    rm = fmaxf(rm, __shfl_xor_sync(0xffffffffu, rm, off));
                float m_new = fmaxf(m[i], rm);
                float alpha = __expf(m[i] - m_new);
                float rs = 0.f;
                #pragma unroll
                for (int j = 0; j < 4; ++j) {
                    s[i][j] = __expf(s[i][j] - m_new);   // p
                    rs += s[i][j];
                }
                #pragma unroll
                for (int off = 8; off > 0; off >>= 1)
                    rs += __shfl_xor_sync(0xffffffffu, rs, off);
                l[i] = l[i] * alpha + rs;
                m[i] = m_new;
                o[i][0] *= alpha; o[i][1] *= alpha; o[i][2] *= alpha; o[i][3] *= alpha;
            }

            // Stage P transposed: Pt[j][r]
            #pragma unroll
            for (int i = 0; i < 4; ++i)
                #pragma unroll
                for (int j = 0; j < 4; ++j)
                    Pt[(tx * 4 + j) * PAD + ty * 4 + i] = s[i][j];
            __syncthreads();

            // PV: o[r][h] += sum_j Pt[j][r] * Vs[j][h]
            #pragma unroll 8
            for (int j = 0; j < 64; ++j) {
                float4 a = *(const float4*)(Pt + j * PAD + ty * 4);
                float4 v = *(const float4*)(Vs + j * PAD + tx * 4);
                o[0][0] += a.x * v.x; o[0][1] += a.x * v.y; o[0][2] += a.x * v.z; o[0][3] += a.x * v.w;
                o[1][0] += a.y * v.x; o[1][1] += a.y * v.y; o[1][2] += a.y * v.z; o[1][3] += a.y * v.w;
                o[2][0] += a.z * v.x; o[2][1] += a.z * v.y; o[2][2] += a.z * v.z; o[2][3] += a.z * v.w;
                o[3][0] += a.w * v.x; o[3][1] += a.w * v.y; o[3][2] += a.w * v.z; o[3][3] += a.w * v.w;
            }
        }

        // Epilogue: out[r][h] = o / l
        #pragma unroll
        for (int i = 0; i < 4; ++i) {
            float inv = 1.0f / l[i];
            float4 r;
            r.x = o[i][0] * inv; r.y = o[i][1] * inv;
            r.z = o[i][2] * inv; r.w = o[i][3] * inv;
            *(float4*)(out + ((size_t)b * T_ + q0 + ty * 4 + i) * H_ + tx * 4) = r;
        }
    }
}

// ---------------------------------------------------------------------------
extern "C" void kernel_launch(void* const* d_in, const int* in_sizes, int n_in,
                              void* d_out, int out_size)
{
    const float* x  = (const float*)d_in[0];
    const float* wq = (const float*)d_in[1];
    const float* bq = (const float*)d_in[2];
    const float* wk = (const float*)d_in[3];
    const float* bk = (const float*)d_in[4];
    const float* wv = (const float*)d_in[5];
    const float* bv = (const float*)d_in[6];
    float* out = (float*)d_out;

    // Projections: 256 M-tiles x {q,k,v}
    proj_kernel<<<dim3(256, 3), 256>>>(x, wq, bq, wk, bk, wv, bv);

    // Attention: 16 balanced q-tile pairs x 8 batches
    const size_t smem = 4 * SM_TILE * sizeof(float);   // 69,632 B
    cudaFuncSetAttribute(attn_kernel, cudaFuncAttributeMaxDynamicSharedMemorySize, (int)smem);
    attn_kernel<<<dim3(16, 8), 256, smem>>>(out);
}

// round 3
// speedup vs baseline: 1.6548x; 1.6548x over previous
#include <cuda_runtime.h>
#include <cuda_bf16.h>
#include <math.h>
#include <stdint.h>

// Problem constants
#define B_   8
#define T_   2048
#define C_   1024
#define H_   64
#define NROW (B_ * T_)          // 16384
#define PAD  68                 // smem row pad for SIMT attention (floats)

// Scratch: projected Q,K,V (fp32) + pre-split weights (bf16 hi/lo, [mat][n][k])
__device__ float g_Q[NROW * H_];
__device__ float g_K[NROW * H_];
__device__ float g_V[NROW * H_];
__device__ __nv_bfloat16 g_Wh[3 * H_ * C_];
__device__ __nv_bfloat16 g_Wl[3 * H_ * C_];

__device__ __forceinline__ uint32_t smem_u32(const void* p) {
    uint32_t a;
    asm("{ .reg .u64 t; cvta.to.shared.u64 t, %1; cvt.u32.u64 %0, t; }" : "=r"(a) : "l"(p));
    return a;
}

// ---------------------------------------------------------------------------
// Prep: split weights fp32 -> bf16 hi/lo, transpose [k][n] -> [mat][n][k]
// ---------------------------------------------------------------------------
__global__ void prep_w(const float* __restrict__ wq,
                       const float* __restrict__ wk,
                       const float* __restrict__ wv)
{
    int e = blockIdx.x * 256 + threadIdx.x;
    if (e >= 3 * H_ * C_) return;
    int mat = e / (H_ * C_);
    int r   = e % (H_ * C_);
    int n   = r / C_;
    int k   = r % C_;
    const float* w = (mat == 0) ? wq : (mat == 1) ? wk : wv;
    float v = w[k * H_ + n];
    __nv_bfloat16 h = __float2bfloat16(v);
    g_Wh[e] = h;
    g_Wl[e] = __float2bfloat16(v - __bfloat162float(h));
}

// ---------------------------------------------------------------------------
// Projection via mma.sync (HMMA bf16, fp32 acc), hi/lo split for fp32 accuracy.
// One CTA: 128 rows x 64 cols x 3 matrices (x converted once, reused 3x).
// 256 threads = 8 warps; warp w owns rows w*16..w*16+15, all 64 cols.
// grid = 128.
// ---------------------------------------------------------------------------
#define KP    72                    // bf16 elems per smem row (144B, conflict-free LDSM)
#define XH_OFF 0
#define XL_OFF (128 * KP * 2)                       // 18432
#define WH_OFF (2 * 128 * KP * 2)                   // 36864
#define WL_OFF (WH_OFF + 3 * 64 * KP * 2)           // 64512
#define PROJ_SMEM (WL_OFF + 3 * 64 * KP * 2)        // 92160

__device__ __forceinline__ void ldsm4(uint32_t& r0, uint32_t& r1, uint32_t& r2,
                                      uint32_t& r3, uint32_t addr) {
    asm volatile("ldmatrix.sync.aligned.m8n8.x4.shared.b16 {%0,%1,%2,%3}, [%4];"
                 : "=r"(r0), "=r"(r1), "=r"(r2), "=r"(r3) : "r"(addr));
}
__device__ __forceinline__ void mma16816(float* d, uint32_t a0, uint32_t a1,
                                         uint32_t a2, uint32_t a3,
                                         uint32_t b0, uint32_t b1) {
    asm volatile("mma.sync.aligned.m16n8k16.row.col.f32.bf16.bf16.f32 "
                 "{%0,%1,%2,%3}, {%4,%5,%6,%7}, {%8,%9}, {%0,%1,%2,%3};"
                 : "+f"(d[0]), "+f"(d[1]), "+f"(d[2]), "+f"(d[3])
                 : "r"(a0), "r"(a1), "r"(a2), "r"(a3), "r"(b0), "r"(b1));
}

__global__ __launch_bounds__(256) void proj_mma(
    const float* __restrict__ x,
    const float* __restrict__ bq,
    const float* __restrict__ bk,
    const float* __restrict__ bv)
{
    extern __shared__ char smc[];
    const uint32_t sb = smem_u32(smc);
    const int tid  = threadIdx.x;
    const int wid  = tid >> 5;
    const int lane = tid & 31;
    const int m0   = blockIdx.x * 128;

    float acc[3][8][4];
    #pragma unroll
    for (int m = 0; m < 3; ++m)
        #pragma unroll
        for (int n = 0; n < 8; ++n)
            #pragma unroll
            for (int i = 0; i < 4; ++i) acc[m][n][i] = 0.f;

    // Per-lane LDSM source addresses (byte offsets within smem)
    // A (x): lanes 0-15 -> row lane, half 0; lanes 16-31 -> row lane-16, half 1
    const int a_row  = lane & 15;
    const int a_half = lane >> 4;
    const uint32_t a_base = sb + XH_OFF + ((wid * 16 + a_row) * KP + a_half * 8) * 2;
    // B (w^T [n][k]): grp 0: n=l8 h0 | grp1: n=l8 h1 | grp2: n=8+l8 h0 | grp3: n=8+l8 h1
    const int l8   = lane & 7;
    const int bgrp = lane >> 3;
    const int b_n  = ((bgrp & 2) ? 8 : 0) + l8;
    const int b_h  = bgrp & 1;
    const uint32_t b_base = sb + ((b_n)*KP + b_h * 8) * 2;   // add WH/WL + mat/nb2/ks offsets

    #pragma unroll 1
    for (int kc = 0; kc < C_; kc += 64) {
        __syncthreads();
        // --- stage x chunk [128][64] as bf16 hi/lo (rows padded to KP) ---
        #pragma unroll
        for (int it = 0; it < 8; ++it) {
            int u  = tid + it * 256;          // 0..2047 float4 units
            int r  = u >> 4;
            int c4 = (u & 15) << 2;
            float4 t = *(const float4*)(x + (size_t)(m0 + r) * C_ + kc + c4);
            __nv_bfloat16 h0 = __float2bfloat16(t.x);
            __nv_bfloat16 h1 = __float2bfloat16(t.y);
            __nv_bfloat16 h2 = __float2bfloat16(t.z);
            __nv_bfloat16 h3 = __float2bfloat16(t.w);
            __nv_bfloat162 H01(h0, h1), H23(h2, h3);
            __nv_bfloat162 L01(__float2bfloat16(t.x - __bfloat162float(h0)),
                               __float2bfloat16(t.y - __bfloat162float(h1)));
            __nv_bfloat162 L23(__float2bfloat16(t.z - __bfloat162float(h2)),
                               __float2bfloat16(t.w - __bfloat162float(h3)));
            int off = (r * KP + c4) * 2;
            uint2 hh = make_uint2(*(uint32_t*)&H01, *(uint32_t*)&H23);
            uint2 ll = make_uint2(*(uint32_t*)&L01, *(uint32_t*)&L23);
            *(uint2*)(smc + XH_OFF + off) = hh;
            *(uint2*)(smc + XL_OFF + off) = ll;
        }
        // --- stage w^T chunks [3][64][64] hi/lo ---
        #pragma unroll
        for (int it = 0; it < 6; ++it) {
            int u   = tid + it * 256;         // 0..1535 16B units
            int mat = u >> 9;
            int rem = u & 511;
            int n   = rem >> 3;
            int kg  = (rem & 7) * 8;          // bf16 elems
            size_t src = (size_t)mat * (H_ * C_) + (size_t)n * C_ + kc + kg;
            int dst = ((mat * 64 + n) * KP + kg) * 2;
            *(uint4*)(smc + WH_OFF + dst) = *(const uint4*)(g_Wh + src);
            *(uint4*)(smc + WL_OFF + dst) = *(const uint4*)(g_Wl + src);
        }
        __syncthreads();

        #pragma unroll
        for (int ks = 0; ks < 4; ++ks) {
            uint32_t ah0, ah1, ah2, ah3, al0, al1, al2, al3;
            ldsm4(ah0, ah1, ah2, ah3, a_base + ks * 32);
            ldsm4(al0, al1, al2, al3, a_base + (XL_OFF - XH_OFF) + ks * 32);
            #pragma unroll
            for (int mat = 0; mat < 3; ++mat) {
                #pragma unroll
                for (int nb2 = 0; nb2 < 4; ++nb2) {
                    uint32_t off = (mat * 64 + nb2 * 16) * (KP * 2) + ks * 32;
                    uint32_t bh0, bh1, bh2, bh3, bl0, bl1, bl2, bl3;
                    ldsm4(bh0, bh1, bh2, bh3, b_base + WH_OFF + off);
                    ldsm4(bl0, bl1, bl2, bl3, b_base + WL_OFF + off);
                    // n-block nb2*2
                    mma16816(acc[mat][nb2 * 2],     ah0, ah1, ah2, ah3, bh0, bh1);
                    mma16816(acc[mat][nb2 * 2],     ah0, ah1, ah2, ah3, bl0, bl1);
                    mma16816(acc[mat][nb2 * 2],     al0, al1, al2, al3, bh0, bh1);
                    // n-block nb2*2+1
                    mma16816(acc[mat][nb2 * 2 + 1], ah0, ah1, ah2, ah3, bh2, bh3);
                    mma16816(acc[mat][nb2 * 2 + 1], ah0, ah1, ah2, ah3, bl2, bl3);
                    mma16816(acc[mat][nb2 * 2 + 1], al0, al1, al2, al3, bh2, bh3);
                }
            }
        }
    }

    // --- epilogue: add bias, store fp32 ---
    const int g  = lane >> 2;
    const int tg = lane & 3;
    const int row = m0 + wid * 16 + g;
    #pragma unroll
    for (int mat = 0; mat < 3; ++mat) {
        const float* bias = (mat == 0) ? bq : (mat == 1) ? bk : bv;
        float* dst        = (mat == 0) ? g_Q : (mat == 1) ? g_K : g_V;
        #pragma unroll
        for (int nb = 0; nb < 8; ++nb) {
            int col = nb * 8 + tg * 2;
            float b0 = __ldg(bias + col);
            float b1 = __ldg(bias + col + 1);
            float2 lo = make_float2(acc[mat][nb][0] + b0, acc[mat][nb][1] + b1);
            float2 hi = make_float2(acc[mat][nb][2] + b0, acc[mat][nb][3] + b1);
            *(float2*)(dst + (size_t)row * H_ + col)       = lo;
            *(float2*)(dst + (size_t)(row + 8) * H_ + col) = hi;
        }
    }
}

// ---------------------------------------------------------------------------
// Flash-style causal attention (unchanged, verified in R1).
// ---------------------------------------------------------------------------
#define SM_TILE (64 * PAD)

__global__ __launch_bounds__(256) void attn_kernel(float* __restrict__ out)
{
    extern __shared__ float smf[];
    float* Qt = smf;
    float* Kt = smf + SM_TILE;
    float* Vs = smf + 2 * SM_TILE;
    float* Pt = smf + 3 * SM_TILE;

    const int b   = blockIdx.y;
    const int px  = blockIdx.x;
    const int tid = threadIdx.x;
    const int tx  = tid & 15;
    const int ty  = tid >> 4;
    const float scale = 0.03125f;

    #pragma unroll 1
    for (int half = 0; half < 2; ++half) {
        const int qt = half ? (31 - px) : px;
        const int q0 = qt * 64;
        const float* __restrict__ Qg = g_Q + ((size_t)b * T_ + q0) * H_;

        __syncthreads();
        #pragma unroll
        for (int it = 0; it < 4; ++it) {
            int v  = tid + it * 256;
            int r  = v >> 4;
            int h4 = (v & 15) << 2;
            float4 t = *(const float4*)(Qg + r * H_ + h4);
            Qt[(h4 + 0) * PAD + r] = t.x;
            Qt[(h4 + 1) * PAD + r] = t.y;
            Qt[(h4 + 2) * PAD + r] = t.z;
            Qt[(h4 + 3) * PAD + r] = t.w;
        }

        float m[4], l[4], o[4][4];
        #pragma unroll
        for (int i = 0; i < 4; ++i) {
            m[i] = -INFINITY; l[i] = 0.f;
            o[i][0] = o[i][1] = o[i][2] = o[i][3] = 0.f;
        }

        #pragma unroll 1
        for (int kt = 0; kt <= qt; ++kt) {
            const int kb = kt * 64;
            const float* __restrict__ Kg = g_K + ((size_t)b * T_ + kb) * H_;
            const float* __restrict__ Vg = g_V + ((size_t)b * T_ + kb) * H_;

            __syncthreads();
            #pragma unroll
            for (int it = 0; it < 4; ++it) {
                int v  = tid + it * 256;
                int j  = v >> 4;
                int h4 = (v & 15) << 2;
                float4 t = *(const float4*)(Kg + j * H_ + h4);
                Kt[(h4 + 0) * PAD + j] = t.x;
                Kt[(h4 + 1) * PAD + j] = t.y;
                Kt[(h4 + 2) * PAD + j] = t.z;
                Kt[(h4 + 3) * PAD + j] = t.w;
                float4 u = *(const float4*)(Vg + j * H_ + h4);
                *(float4*)(Vs + j * PAD + h4) = u;
            }
            __syncthreads();

            float s[4][4] = {};
            #pragma unroll 8
            for (int h = 0; h < 64; ++h) {
                float4 a = *(const float4*)(Qt + h * PAD + ty * 4);
                float4 k = *(const float4*)(Kt + h * PAD + tx * 4);
                s[0][0] += a.x * k.x; s[0][1] += a.x * k.y; s[0][2] += a.x * k.z; s[0][3] += a.x * k.w;
                s[1][0] += a.y * k.x; s[1][1] += a.y * k.y; s[1][2] += a.y * k.z; s[1][3] += a.y * k.w;
                s[2][0] += a.z * k.x; s[2][1] += a.z * k.y; s[2][2] += a.z * k.z; s[2][3] += a.z * k.w;
                s[3][0] += a.w * k.x; s[3][1] += a.w * k.y; s[3][2] += a.w * k.z; s[3][3] += a.w * k.w;
            }
            #pragma unroll
            for (int i = 0; i < 4; ++i)
                #pragma unroll
                for (int j = 0; j < 4; ++j)
                    s[i][j] *= scale;

            if (kt == qt) {
                #pragma unroll
                for (int i = 0; i < 4; ++i)
                    #pragma unroll
                    for (int j = 0; j < 4; ++j)
                        if (kb + tx * 4 + j > q0 + ty * 4 + i) s[i][j] = -INFINITY;
            }

            #pragma unroll
            for (int i = 0; i < 4; ++i) {
                float rm = fmaxf(fmaxf(s[i][0], s[i][1]), fmaxf(s[i][2], s[i][3]));
                #pragma unroll
                for (int off = 8; off > 0; off >>= 1)
                    rm = fmaxf(rm, __shfl_xor_sync(0xffffffffu, rm, off));
                float m_new = fmaxf(m[i], rm);
                float alpha = __expf(m[i] - m_new);
                float rs = 0.f;
                #pragma unroll
                for (int j = 0; j < 4; ++j) {
                    s[i][j] = __expf(s[i][j] - m_new);
                    rs += s[i][j];
                }
                #pragma unroll
                for (int off = 8; off > 0; off >>= 1)
                    rs += __shfl_xor_sync(0xffffffffu, rs, off);
                l[i] = l[i] * alpha + rs;
                m[i] = m_new;
                o[i][0] *= alpha; o[i][1] *= alpha; o[i][2] *= alpha; o[i][3] *= alpha;
            }

            #pragma unroll
            for (int i = 0; i < 4; ++i)
                #pragma unroll
                for (int j = 0; j < 4; ++j)
                    Pt[(tx * 4 + j) * PAD + ty * 4 + i] = s[i][j];
            __syncthreads();

            #pragma unroll 8
            for (int j = 0; j < 64; ++j) {
                float4 a = *(const float4*)(Pt + j * PAD + ty * 4);
                float4 v = *(const float4*)(Vs + j * PAD + tx * 4);
                o[0][0] += a.x * v.x; o[0][1] += a.x * v.y; o[0][2] += a.x * v.z; o[0][3] += a.x * v.w;
                o[1][0] += a.y * v.x; o[1][1] += a.y * v.y; o[1][2] += a.y * v.z; o[1][3] += a.y * v.w;
                o[2][0] += a.z * v.x; o[2][1] += a.z * v.y; o[2][2] += a.z * v.z; o[2][3] += a.z * v.w;
                o[3][0] += a.w * v.x; o[3][1] += a.w * v.y; o[3][2] += a.w * v.z; o[3][3] += a.w * v.w;
            }
        }

        #pragma unroll
        for (int i = 0; i < 4; ++i) {
            float inv = 1.0f / l[i];
            float4 r;
            r.x = o[i][0] * inv; r.y = o[i][1] * inv;
            r.z = o[i][2] * inv; r.w = o[i][3] * inv;
            *(float4*)(out + ((size_t)b * T_ + q0 + ty * 4 + i) * H_ + tx * 4) = r;
        }
    }
}

// ---------------------------------------------------------------------------
extern "C" void kernel_launch(void* const* d_in, const int* in_sizes, int n_in,
                              void* d_out, int out_size)
{
    const float* x  = (const float*)d_in[0];
    const float* wq = (const float*)d_in[1];
    const float* bq = (const float*)d_in[2];
    const float* wk = (const float*)d_in[3];
    const float* bk = (const float*)d_in[4];
    const float* wv = (const float*)d_in[5];
    const float* bv = (const float*)d_in[6];
    float* out = (float*)d_out;

    // 1) split weights to bf16 hi/lo ([mat][n][k])
    prep_w<<<(3 * H_ * C_ + 255) / 256, 256>>>(wq, wk, wv);

    // 2) fused Q/K/V projection on HMMA tensor cores (bf16 split, fp32 acc)
    cudaFuncSetAttribute(proj_mma, cudaFuncAttributeMaxDynamicSharedMemorySize, PROJ_SMEM);
    proj_mma<<<128, 256, PROJ_SMEM>>>(x, bq, bk, bv);

    // 3) attention (SIMT flash, balanced q-tile pairs)
    const size_t smem = 4 * SM_TILE * sizeof(float);
    cudaFuncSetAttribute(attn_kernel, cudaFuncAttributeMaxDynamicSharedMemorySize, (int)smem);
    attn_kernel<<<dim3(16, 8), 256, smem>>>(out);
}

// round 4
// speedup vs baseline: 3.1270x; 1.8897x over previous
#include <cuda_runtime.h>
#include <cuda_bf16.h>
#include <math.h>
#include <stdint.h>

// Problem constants
#define B_   8
#define T_   2048
#define C_   1024
#define H_   64
#define NROW (B_ * T_)          // 16384

// Scratch: bf16 hi/lo split Q (pre-scaled by 1/32), K, V; pre-split weights
__device__ __nv_bfloat16 g_Qh[NROW * H_], g_Ql[NROW * H_];
__device__ __nv_bfloat16 g_Kh[NROW * H_], g_Kl[NROW * H_];
__device__ __nv_bfloat16 g_Vh[NROW * H_], g_Vl[NROW * H_];
__device__ __nv_bfloat16 g_Wh[3 * H_ * C_];
__device__ __nv_bfloat16 g_Wl[3 * H_ * C_];

__device__ __forceinline__ uint32_t smem_u32(const void* p) {
    uint32_t a;
    asm("{ .reg .u64 t; cvta.to.shared.u64 t, %1; cvt.u32.u64 %0, t; }" : "=r"(a) : "l"(p));
    return a;
}
__device__ __forceinline__ void ldsm4(uint32_t& r0, uint32_t& r1, uint32_t& r2,
                                      uint32_t& r3, uint32_t addr) {
    asm volatile("ldmatrix.sync.aligned.m8n8.x4.shared.b16 {%0,%1,%2,%3}, [%4];"
                 : "=r"(r0), "=r"(r1), "=r"(r2), "=r"(r3) : "r"(addr));
}
__device__ __forceinline__ void ldsm4t(uint32_t& r0, uint32_t& r1, uint32_t& r2,
                                       uint32_t& r3, uint32_t addr) {
    asm volatile("ldmatrix.sync.aligned.m8n8.x4.trans.shared.b16 {%0,%1,%2,%3}, [%4];"
                 : "=r"(r0), "=r"(r1), "=r"(r2), "=r"(r3) : "r"(addr));
}
__device__ __forceinline__ void mma16816(float* d, uint32_t a0, uint32_t a1,
                                         uint32_t a2, uint32_t a3,
                                         uint32_t b0, uint32_t b1) {
    asm volatile("mma.sync.aligned.m16n8k16.row.col.f32.bf16.bf16.f32 "
                 "{%0,%1,%2,%3}, {%4,%5,%6,%7}, {%8,%9}, {%0,%1,%2,%3};"
                 : "+f"(d[0]), "+f"(d[1]), "+f"(d[2]), "+f"(d[3])
                 : "r"(a0), "r"(a1), "r"(a2), "r"(a3), "r"(b0), "r"(b1));
}
// pack two fp32 -> bf16x2 (lo -> low half, hi -> high half)
__device__ __forceinline__ uint32_t pk2(float lo, float hi) {
    uint32_t r;
    asm("cvt.rn.bf16x2.f32 %0, %1, %2;" : "=r"(r) : "f"(hi), "f"(lo));
    return r;
}
__device__ __forceinline__ float bfround(float v) {
    return __bfloat162float(__float2bfloat16(v));
}
__device__ __forceinline__ uint32_t pack_bf16(__nv_bfloat16 a, __nv_bfloat16 b) {
    __nv_bfloat162 t; t.x = a; t.y = b;
    return *(uint32_t*)&t;
}

// ---------------------------------------------------------------------------
// Prep: split weights fp32 -> bf16 hi/lo, transpose [k][n] -> [mat][n][k]
// ---------------------------------------------------------------------------
__global__ void prep_w(const float* __restrict__ wq,
                       const float* __restrict__ wk,
                       const float* __restrict__ wv)
{
    int e = blockIdx.x * 256 + threadIdx.x;
    if (e >= 3 * H_ * C_) return;
    int mat = e / (H_ * C_);
    int r   = e % (H_ * C_);
    int n   = r / C_;
    int k   = r % C_;
    const float* w = (mat == 0) ? wq : (mat == 1) ? wk : wv;
    float v = w[k * H_ + n];
    __nv_bfloat16 h = __float2bfloat16(v);
    g_Wh[e] = h;
    g_Wl[e] = __float2bfloat16(v - __bfloat162float(h));
}

// ---------------------------------------------------------------------------
// Projection via mma.sync (bf16 hi/lo split, fp32 acc). Epilogue writes
// Q (pre-scaled 1/32), K, V as bf16 hi/lo pairs for the attention kernel.
// ---------------------------------------------------------------------------
#define KP    72
#define XH_OFF 0
#define XL_OFF (128 * KP * 2)
#define WH_OFF (2 * 128 * KP * 2)
#define WL_OFF (WH_OFF + 3 * 64 * KP * 2)
#define PROJ_SMEM (WL_OFF + 3 * 64 * KP * 2)   // 92160

__global__ __launch_bounds__(256) void proj_mma(
    const float* __restrict__ x,
    const float* __restrict__ bq,
    const float* __restrict__ bk,
    const float* __restrict__ bv)
{
    extern __shared__ char smc[];
    const uint32_t sb = smem_u32(smc);
    const int tid  = threadIdx.x;
    const int wid  = tid >> 5;
    const int lane = tid & 31;
    const int m0   = blockIdx.x * 128;

    float acc[3][8][4];
    #pragma unroll
    for (int m = 0; m < 3; ++m)
        #pragma unroll
        for (int n = 0; n < 8; ++n)
            #pragma unroll
            for (int i = 0; i < 4; ++i) acc[m][n][i] = 0.f;

    const int a_row  = lane & 15;
    const int a_half = lane >> 4;
    const uint32_t a_base = sb + XH_OFF + ((wid * 16 + a_row) * KP + a_half * 8) * 2;
    const int l8   = lane & 7;
    const int bgrp = lane >> 3;
    const int b_n  = ((bgrp & 2) ? 8 : 0) + l8;
    const int b_h  = bgrp & 1;
    const uint32_t b_base = sb + ((b_n)*KP + b_h * 8) * 2;

    #pragma unroll 1
    for (int kc = 0; kc < C_; kc += 64) {
        __syncthreads();
        #pragma unroll
        for (int it = 0; it < 8; ++it) {
            int u  = tid + it * 256;
            int r  = u >> 4;
            int c4 = (u & 15) << 2;
            float4 t = *(const float4*)(x + (size_t)(m0 + r) * C_ + kc + c4);
            __nv_bfloat16 h0 = __float2bfloat16(t.x);
            __nv_bfloat16 h1 = __float2bfloat16(t.y);
            __nv_bfloat16 h2 = __float2bfloat16(t.z);
            __nv_bfloat16 h3 = __float2bfloat16(t.w);
            __nv_bfloat162 H01(h0, h1), H23(h2, h3);
            __nv_bfloat162 L01(__float2bfloat16(t.x - __bfloat162float(h0)),
                               __float2bfloat16(t.y - __bfloat162float(h1)));
            __nv_bfloat162 L23(__float2bfloat16(t.z - __bfloat162float(h2)),
                               __float2bfloat16(t.w - __bfloat162float(h3)));
            int off = (r * KP + c4) * 2;
            uint2 hh = make_uint2(*(uint32_t*)&H01, *(uint32_t*)&H23);
            uint2 ll = make_uint2(*(uint32_t*)&L01, *(uint32_t*)&L23);
            *(uint2*)(smc + XH_OFF + off) = hh;
            *(uint2*)(smc + XL_OFF + off) = ll;
        }
        #pragma unroll
        for (int it = 0; it < 6; ++it) {
            int u   = tid + it * 256;
            int mat = u >> 9;
            int rem = u & 511;
            int n   = rem >> 3;
            int kg  = (rem & 7) * 8;
            size_t src = (size_t)mat * (H_ * C_) + (size_t)n * C_ + kc + kg;
            int dst = ((mat * 64 + n) * KP + kg) * 2;
            *(uint4*)(smc + WH_OFF + dst) = *(const uint4*)(g_Wh + src);
            *(uint4*)(smc + WL_OFF + dst) = *(const uint4*)(g_Wl + src);
        }
        __syncthreads();

        #pragma unroll
        for (int ks = 0; ks < 4; ++ks) {
            uint32_t ah0, ah1, ah2, ah3, al0, al1, al2, al3;
            ldsm4(ah0, ah1, ah2, ah3, a_base + ks * 32);
            ldsm4(al0, al1, al2, al3, a_base + (XL_OFF - XH_OFF) + ks * 32);
            #pragma unroll
            for (int mat = 0; mat < 3; ++mat) {
                #pragma unroll
                for (int nb2 = 0; nb2 < 4; ++nb2) {
                    uint32_t off = (mat * 64 + nb2 * 16) * (KP * 2) + ks * 32;
                    uint32_t bh0, bh1, bh2, bh3, bl0, bl1, bl2, bl3;
                    ldsm4(bh0, bh1, bh2, bh3, b_base + WH_OFF + off);
                    ldsm4(bl0, bl1, bl2, bl3, b_base + WL_OFF + off);
                    mma16816(acc[mat][nb2 * 2],     ah0, ah1, ah2, ah3, bh0, bh1);
                    mma16816(acc[mat][nb2 * 2],     ah0, ah1, ah2, ah3, bl0, bl1);
                    mma16816(acc[mat][nb2 * 2],     al0, al1, al2, al3, bh0, bh1);
                    mma16816(acc[mat][nb2 * 2 + 1], ah0, ah1, ah2, ah3, bh2, bh3);
                    mma16816(acc[mat][nb2 * 2 + 1], ah0, ah1, ah2, ah3, bl2, bl3);
                    mma16816(acc[mat][nb2 * 2 + 1], al0, al1, al2, al3, bh2, bh3);
                }
            }
        }
    }

    // --- epilogue: add bias, (Q: fold softmax scale), split hi/lo, store bf16 ---
    const int g  = lane >> 2;
    const int tg = lane & 3;
    const int row = m0 + wid * 16 + g;
    #pragma unroll
    for (int mat = 0; mat < 3; ++mat) {
        const float* bias = (mat == 0) ? bq : (mat == 1) ? bk : bv;
        __nv_bfloat16* dh = (mat == 0) ? g_Qh : (mat == 1) ? g_Kh : g_Vh;
        __nv_bfloat16* dl = (mat == 0) ? g_Ql : (mat == 1) ? g_Kl : g_Vl;
        const float scl = (mat == 0) ? 0.03125f : 1.0f;
        #pragma unroll
        for (int nb = 0; nb < 8; ++nb) {
            int col = nb * 8 + tg * 2;
            float b0 = __ldg(bias + col);
            float b1 = __ldg(bias + col + 1);
            float v0 = (acc[mat][nb][0] + b0) * scl;
            float v1 = (acc[mat][nb][1] + b1) * scl;
            float v2 = (acc[mat][nb][2] + b0) * scl;
            float v3 = (acc[mat][nb][3] + b1) * scl;
            __nv_bfloat16 h0 = __float2bfloat16(v0), h1 = __float2bfloat16(v1);
            __nv_bfloat16 h2 = __float2bfloat16(v2), h3 = __float2bfloat16(v3);
            size_t o0 = (size_t)row * H_ + col;
            size_t o1 = (size_t)(row + 8) * H_ + col;
            *(uint32_t*)(dh + o0) = pack_bf16(h0, h1);
            *(uint32_t*)(dh + o1) = pack_bf16(h2, h3);
            *(uint32_t*)(dl + o0) = pack_bf16(
                __float2bfloat16(v0 - __bfloat162float(h0)),
                __float2bfloat16(v1 - __bfloat162float(h1)));
            *(uint32_t*)(dl + o1) = pack_bf16(
                __float2bfloat16(v2 - __bfloat162float(h2)),
                __float2bfloat16(v3 - __bfloat162float(h3)));
        }
    }
}

// ---------------------------------------------------------------------------
// HMMA flash attention. CTA = 128 threads (4 warps), q-tile 64 rows (warp=16).
// Pair (qt, 31-qt) -> uniform 33 k-tiles of 64 keys. cp.async double buffer.
// Q pre-scaled by 1/32; all matmuls bf16 hi/lo split, fp32 accumulate.
// grid = (16, 8)
// ---------------------------------------------------------------------------
#define KVROW 144                 // bytes per padded 64-elem bf16 row
#define ARR_B (64 * KVROW)        // 9216 per array
#define BUF_B (4 * ARR_B)         // 36864: Kh,Kl,Vh,Vl
#define ATTN_SMEM (2 * BUF_B)     // 73728

__global__ __launch_bounds__(128) void attn_mma(float* __restrict__ out)
{
    extern __shared__ __align__(16) char smk[];
    const uint32_t sb = smem_u32(smk);
    const int tid  = threadIdx.x;
    const int lane = tid & 31;
    const int wid  = tid >> 5;
    const int b    = blockIdx.y;
    const int px   = blockIdx.x;
    const int g    = lane >> 2;
    const int tg   = lane & 3;
    const int l8   = lane & 7;
    const int bgrp = lane >> 3;
    // K (non-trans B-frag) lane addressing
    const int k_row = ((bgrp & 2) ? 8 : 0) + l8;
    const int k_col = (bgrp & 1) * 16;
    // V (trans B-frag) lane addressing
    const int v_row = ((bgrp & 1) ? 8 : 0) + l8;
    const int v_col = (bgrp & 2) ? 16 : 0;
    const int bt0   = b * T_;

    #pragma unroll 1
    for (int half = 0; half < 2; ++half) {
        const int qt = half ? (31 - px) : px;
        const int q0 = qt * 64;
        const int nk = qt + 1;

        // ---- Q fragments (registers, hi/lo), rows wid*16..+15 ----
        uint32_t qh[4][4], ql[4][4];
        {
            const uint32_t* qhp = (const uint32_t*)g_Qh + (size_t)(bt0 + q0 + wid * 16) * 32;
            const uint32_t* qlp = (const uint32_t*)g_Ql + (size_t)(bt0 + q0 + wid * 16) * 32;
            #pragma unroll
            for (int ks = 0; ks < 4; ++ks) {
                int i0 = g * 32 + ks * 8 + tg;
                int i1 = (g + 8) * 32 + ks * 8 + tg;
                qh[ks][0] = qhp[i0];     qh[ks][1] = qhp[i1];
                qh[ks][2] = qhp[i0 + 4]; qh[ks][3] = qhp[i1 + 4];
                ql[ks][0] = qlp[i0];     ql[ks][1] = qlp[i1];
                ql[ks][2] = qlp[i0 + 4]; ql[ks][3] = qlp[i1 + 4];
            }
        }

        float m0 = -INFINITY, m1 = -INFINITY, l0 = 0.f, l1 = 0.f;
        float o[8][4];
        #pragma unroll
        for (int nb = 0; nb < 8; ++nb)
            o[nb][0] = o[nb][1] = o[nb][2] = o[nb][3] = 0.f;

        // ---- cp.async tile loader ----
        auto issue_tile = [&](int kt2, int buf) {
            uint32_t db = sb + buf * BUF_B;
            size_t r0 = (size_t)(bt0 + kt2 * 64);
            #pragma unroll
            for (int arr = 0; arr < 4; ++arr) {
                const __nv_bfloat16* sp = (arr == 0) ? g_Kh : (arr == 1) ? g_Kl
                                        : (arr == 2) ? g_Vh : g_Vl;
                #pragma unroll
                for (int j = 0; j < 4; ++j) {
                    int rem = tid + j * 128;       // 0..511
                    int row = rem >> 3;
                    int c8  = rem & 7;
                    uint32_t d = db + arr * ARR_B + row * KVROW + c8 * 16;
                    const void* s = sp + (r0 + row) * 64 + c8 * 8;
                    asm volatile("cp.async.cg.shared.global [%0], [%1], 16;"
                                 :: "r"(d), "l"(s) : "memory");
                }
            }
            asm volatile("cp.async.commit_group;" ::: "memory");
        };

        issue_tile(0, 0);

        #pragma unroll 1
        for (int kt = 0; kt < nk; ++kt) {
            if (kt + 1 < nk) {
                issue_tile(kt + 1, (kt + 1) & 1);
                asm volatile("cp.async.wait_group 1;" ::: "memory");
            } else {
                asm volatile("cp.async.wait_group 0;" ::: "memory");
            }
            __syncthreads();

            const uint32_t kb_s = sb + (kt & 1) * BUF_B;          // Kh base
            const uint32_t kv_s = kb_s + 2 * ARR_B;               // Vh base

            // ---- S = Q.K^T (hi/lo split) ----
            float s[8][4];
            #pragma unroll
            for (int nb = 0; nb < 8; ++nb)
                s[nb][0] = s[nb][1] = s[nb][2] = s[nb][3] = 0.f;

            #pragma unroll
            for (int ks = 0; ks < 4; ++ks) {
                #pragma unroll
                for (int np = 0; np < 4; ++np) {
                    uint32_t aH = kb_s + (np * 16 + k_row) * KVROW + k_col + ks * 32;
                    uint32_t bh0, bh1, bh2, bh3, bl0, bl1, bl2, bl3;
                    ldsm4(bh0, bh1, bh2, bh3, aH);
                    ldsm4(bl0, bl1, bl2, bl3, aH + ARR_B);
                    mma16816(s[np * 2],     qh[ks][0], qh[ks][1], qh[ks][2], qh[ks][3], bh0, bh1);
                    mma16816(s[np * 2],     qh[ks][0], qh[ks][1], qh[ks][2], qh[ks][3], bl0, bl1);
                    mma16816(s[np * 2],     ql[ks][0], ql[ks][1], ql[ks][2], ql[ks][3], bh0, bh1);
                    mma16816(s[np * 2 + 1], qh[ks][0], qh[ks][1], qh[ks][2], qh[ks][3], bh2, bh3);
                    mma16816(s[np * 2 + 1], qh[ks][0], qh[ks][1], qh[ks][2], qh[ks][3], bl2, bl3);
                    mma16816(s[np * 2 + 1], ql[ks][0], ql[ks][1], ql[ks][2], ql[ks][3], bh2, bh3);
                }
            }

            // ---- causal mask on diagonal tile ----
            if (kt == qt) {
                const int r0 = wid * 16 + g;
                const int r1 = r0 + 8;
                #pragma unroll
                for (int nb = 0; nb < 8; ++nb) {
                    int c0 = nb * 8 + tg * 2;
                    if (c0     > r0) s[nb][0] = -INFINITY;
                    if (c0 + 1 > r0) s[nb][1] = -INFINITY;
                    if (c0     > r1) s[nb][2] = -INFINITY;
                    if (c0 + 1 > r1) s[nb][3] = -INFINITY;
                }
            }

            // ---- online softmax (fp32) ----
            float rm0 = -INFINITY, rm1 = -INFINITY;
            #pragma unroll
            for (int nb = 0; nb < 8; ++nb) {
                rm0 = fmaxf(rm0, fmaxf(s[nb][0], s[nb][1]));
                rm1 = fmaxf(rm1, fmaxf(s[nb][2], s[nb][3]));
            }
            rm0 = fmaxf(rm0, __shfl_xor_sync(0xffffffffu, rm0, 1));
            rm0 = fmaxf(rm0, __shfl_xor_sync(0xffffffffu, rm0, 2));
            rm1 = fmaxf(rm1, __shfl_xor_sync(0xffffffffu, rm1, 1));
            rm1 = fmaxf(rm1, __shfl_xor_sync(0xffffffffu, rm1, 2));
            float mn0 = fmaxf(m0, rm0), mn1 = fmaxf(m1, rm1);
            float al0 = __expf(m0 - mn0), al1 = __expf(m1 - mn1);
            float rs0 = 0.f, rs1 = 0.f;
            #pragma unroll
            for (int nb = 0; nb < 8; ++nb) {
                s[nb][0] = __expf(s[nb][0] - mn0);
                s[nb][1] = __expf(s[nb][1] - mn0);
                s[nb][2] = __expf(s[nb][2] - mn1);
                s[nb][3] = __expf(s[nb][3] - mn1);
                rs0 += s[nb][0] + s[nb][1];
                rs1 += s[nb][2] + s[nb][3];
            }
            rs0 += __shfl_xor_sync(0xffffffffu, rs0, 1);
            rs0 += __shfl_xor_sync(0xffffffffu, rs0, 2);
            rs1 += __shfl_xor_sync(0xffffffffu, rs1, 1);
            rs1 += __shfl_xor_sync(0xffffffffu, rs1, 2);
            l0 = l0 * al0 + rs0; m0 = mn0;
            l1 = l1 * al1 + rs1; m1 = mn1;
            #pragma unroll
            for (int nb = 0; nb < 8; ++nb) {
                o[nb][0] *= al0; o[nb][1] *= al0;
                o[nb][2] *= al1; o[nb][3] *= al1;
            }

            // ---- O += P.V (P in registers, hi/lo split; V via ldmatrix.trans) ----
            #pragma unroll
            for (int ks = 0; ks < 4; ++ks) {
                float p00 = s[2 * ks][0],     p01 = s[2 * ks][1];
                float p02 = s[2 * ks][2],     p03 = s[2 * ks][3];
                float p10 = s[2 * ks + 1][0], p11 = s[2 * ks + 1][1];
                float p12 = s[2 * ks + 1][2], p13 = s[2 * ks + 1][3];
                uint32_t pah0 = pk2(p00, p01), pah1 = pk2(p02, p03);
                uint32_t pah2 = pk2(p10, p11), pah3 = pk2(p12, p13);
                uint32_t pal0 = pk2(p00 - bfround(p00), p01 - bfround(p01));
                uint32_t pal1 = pk2(p02 - bfround(p02), p03 - bfround(p03));
                uint32_t pal2 = pk2(p10 - bfround(p10), p11 - bfround(p11));
                uint32_t pal3 = pk2(p12 - bfround(p12), p13 - bfround(p13));
                #pragma unroll
                for (int hp = 0; hp < 4; ++hp) {
                    uint32_t aV = kv_s + (ks * 16 + v_row) * KVROW + v_col + hp * 32;
                    uint32_t vh0, vh1, vh2, vh3, vl0, vl1, vl2, vl3;
                    ldsm4t(vh0, vh1, vh2, vh3, aV);
                    ldsm4t(vl0, vl1, vl2, vl3, aV + ARR_B);
                    mma16816(o[hp * 2],     pah0, pah1, pah2, pah3, vh0, vh1);
                    mma16816(o[hp * 2],     pah0, pah1, pah2, pah3, vl0, vl1);
                    mma16816(o[hp * 2],     pal0, pal1, pal2, pal3, vh0, vh1);
                    mma16816(o[hp * 2 + 1], pah0, pah1, pah2, pah3, vh2, vh3);
                    mma16816(o[hp * 2 + 1], pah0, pah1, pah2, pah3, vl2, vl3);
                    mma16816(o[hp * 2 + 1], pal0, pal1, pal2, pal3, vh2, vh3);
                }
            }
            __syncthreads();
        }

        // ---- epilogue ----
        float inv0 = 1.0f / l0, inv1 = 1.0f / l1;
        float* orow0 = out + (size_t)(bt0 + q0 + wid * 16 + g) * H_;
        float* orow1 = orow0 + 8 * H_;
        #pragma unroll
        for (int nb = 0; nb < 8; ++nb) {
            int col = nb * 8 + tg * 2;
            *(float2*)(orow0 + col) = make_float2(o[nb][0] * inv0, o[nb][1] * inv0);
            *(float2*)(orow1 + col) = make_float2(o[nb][2] * inv1, o[nb][3] * inv1);
        }
    }
}

// ---------------------------------------------------------------------------
extern "C" void kernel_launch(void* const* d_in, const int* in_sizes, int n_in,
                              void* d_out, int out_size)
{
    const float* x  = (const float*)d_in[0];
    const float* wq = (const float*)d_in[1];
    const float* bq = (const float*)d_in[2];
    const float* wk = (const float*)d_in[3];
    const float* bk = (const float*)d_in[4];
    const float* wv = (const float*)d_in[5];
    const float* bv = (const float*)d_in[6];
    float* out = (float*)d_out;

    prep_w<<<(3 * H_ * C_ + 255) / 256, 256>>>(wq, wk, wv);

    cudaFuncSetAttribute(proj_mma, cudaFuncAttributeMaxDynamicSharedMemorySize, PROJ_SMEM);
    proj_mma<<<128, 256, PROJ_SMEM>>>(x, bq, bk, bv);

    cudaFuncSetAttribute(attn_mma, cudaFuncAttributeMaxDynamicSharedMemorySize, ATTN_SMEM);
    attn_mma<<<dim3(16, 8), 128, ATTN_SMEM>>>(out);
}

// round 5
// speedup vs baseline: 3.5963x; 1.1501x over previous
#include <cuda_runtime.h>
#include <cuda_bf16.h>
#include <math.h>
#include <stdint.h>

// Problem constants
#define B_   8
#define T_   2048
#define C_   1024
#define H_   64
#define NROW (B_ * T_)          // 16384

// Scratch: bf16 hi/lo split Q (pre-scaled by 1/32), K, V; pre-split weights
__device__ __nv_bfloat16 g_Qh[NROW * H_], g_Ql[NROW * H_];
__device__ __nv_bfloat16 g_Kh[NROW * H_], g_Kl[NROW * H_];
__device__ __nv_bfloat16 g_Vh[NROW * H_], g_Vl[NROW * H_];
__device__ __nv_bfloat16 g_Wh[3 * H_ * C_];
__device__ __nv_bfloat16 g_Wl[3 * H_ * C_];

__device__ __forceinline__ uint32_t smem_u32(const void* p) {
    uint32_t a;
    asm("{ .reg .u64 t; cvta.to.shared.u64 t, %1; cvt.u32.u64 %0, t; }" : "=r"(a) : "l"(p));
    return a;
}
__device__ __forceinline__ void ldsm4(uint32_t& r0, uint32_t& r1, uint32_t& r2,
                                      uint32_t& r3, uint32_t addr) {
    asm volatile("ldmatrix.sync.aligned.m8n8.x4.shared.b16 {%0,%1,%2,%3}, [%4];"
                 : "=r"(r0), "=r"(r1), "=r"(r2), "=r"(r3) : "r"(addr));
}
__device__ __forceinline__ void ldsm4t(uint32_t& r0, uint32_t& r1, uint32_t& r2,
                                       uint32_t& r3, uint32_t addr) {
    asm volatile("ldmatrix.sync.aligned.m8n8.x4.trans.shared.b16 {%0,%1,%2,%3}, [%4];"
                 : "=r"(r0), "=r"(r1), "=r"(r2), "=r"(r3) : "r"(addr));
}
__device__ __forceinline__ void mma16816(float* d, uint32_t a0, uint32_t a1,
                                         uint32_t a2, uint32_t a3,
                                         uint32_t b0, uint32_t b1) {
    asm volatile("mma.sync.aligned.m16n8k16.row.col.f32.bf16.bf16.f32 "
                 "{%0,%1,%2,%3}, {%4,%5,%6,%7}, {%8,%9}, {%0,%1,%2,%3};"
                 : "+f"(d[0]), "+f"(d[1]), "+f"(d[2]), "+f"(d[3])
                 : "r"(a0), "r"(a1), "r"(a2), "r"(a3), "r"(b0), "r"(b1));
}
__device__ __forceinline__ uint32_t pk2(float lo, float hi) {
    uint32_t r;
    asm("cvt.rn.bf16x2.f32 %0, %1, %2;" : "=r"(r) : "f"(hi), "f"(lo));
    return r;
}
__device__ __forceinline__ float bfround(float v) {
    return __bfloat162float(__float2bfloat16(v));
}
__device__ __forceinline__ uint32_t pack_bf16(__nv_bfloat16 a, __nv_bfloat16 b) {
    __nv_bfloat162 t; t.x = a; t.y = b;
    return *(uint32_t*)&t;
}
#define CP16(dst, src) \
    asm volatile("cp.async.cg.shared.global [%0], [%1], 16;" :: "r"(dst), "l"(src) : "memory")
#define CP_COMMIT() asm volatile("cp.async.commit_group;" ::: "memory")

// ---------------------------------------------------------------------------
// Prep: split weights fp32 -> bf16 hi/lo, transpose [k][n] -> [mat][n][k]
// ---------------------------------------------------------------------------
__global__ void prep_w(const float* __restrict__ wq,
                       const float* __restrict__ wk,
                       const float* __restrict__ wv)
{
    int e = blockIdx.x * 256 + threadIdx.x;
    if (e >= 3 * H_ * C_) return;
    int mat = e / (H_ * C_);
    int r   = e % (H_ * C_);
    int n   = r / C_;
    int k   = r % C_;
    const float* w = (mat == 0) ? wq : (mat == 1) ? wk : wv;
    float v = w[k * H_ + n];
    __nv_bfloat16 h = __float2bfloat16(v);
    g_Wh[e] = h;
    g_Wl[e] = __float2bfloat16(v - __bfloat162float(h));
}

// ---------------------------------------------------------------------------
// Projection via mma.sync, software-pipelined:
//   W: cp.async double buffer;  x: register prefetch + bf16 hi/lo conversion
//   into double-buffered smem. Epilogue emits Q(1/32-scaled)/K/V bf16 hi/lo.
// grid = 128 CTAs x 256 threads (8 warps, warp = 16 rows).
// ---------------------------------------------------------------------------
#define KP 72
#define XBUF_B 36864                 // hi(18432) + lo(18432) per buffer
#define XB(b)  ((b) * XBUF_B)
#define WBUF_B 55296                 // hi(27648) + lo(27648) per buffer
#define WB(b)  (2 * XBUF_B + (b) * WBUF_B)
#define PROJ_SMEM (2 * XBUF_B + 2 * WBUF_B)   // 184320

__global__ __launch_bounds__(256) void proj_mma(
    const float* __restrict__ x,
    const float* __restrict__ bq,
    const float* __restrict__ bk,
    const float* __restrict__ bv)
{
    extern __shared__ char smc[];
    const uint32_t sb = smem_u32(smc);
    const int tid  = threadIdx.x;
    const int wid  = tid >> 5;
    const int lane = tid & 31;
    const int m0   = blockIdx.x * 128;

    float acc[3][8][4];
    #pragma unroll
    for (int m = 0; m < 3; ++m)
        #pragma unroll
        for (int n = 0; n < 8; ++n)
            #pragma unroll
            for (int i = 0; i < 4; ++i) acc[m][n][i] = 0.f;

    const int a_row  = lane & 15;
    const int a_half = lane >> 4;
    const uint32_t a_off = ((wid * 16 + a_row) * KP + a_half * 8) * 2;
    const int l8   = lane & 7;
    const int bgrp = lane >> 3;
    const int b_n  = ((bgrp & 2) ? 8 : 0) + l8;
    const int b_h  = bgrp & 1;
    const uint32_t b_off = (b_n * KP + b_h * 8) * 2;

    float4 X[8];
    auto ldg_x = [&](int kc) {
        #pragma unroll
        for (int it = 0; it < 8; ++it) {
            int u  = tid + it * 256;
            int r  = u >> 4;
            int c4 = (u & 15) << 2;
            X[it] = *(const float4*)(x + (size_t)(m0 + r) * C_ + kc + c4);
        }
    };
    auto cvt_x = [&](int buf) {
        #pragma unroll
        for (int it = 0; it < 8; ++it) {
            int u  = tid + it * 256;
            int r  = u >> 4;
            int c4 = (u & 15) << 2;
            float4 t = X[it];
            __nv_bfloat16 h0 = __float2bfloat16(t.x);
            __nv_bfloat16 h1 = __float2bfloat16(t.y);
            __nv_bfloat16 h2 = __float2bfloat16(t.z);
            __nv_bfloat16 h3 = __float2bfloat16(t.w);
            uint2 hh = make_uint2(pack_bf16(h0, h1), pack_bf16(h2, h3));
            uint2 ll = make_uint2(
                pack_bf16(__float2bfloat16(t.x - __bfloat162float(h0)),
                          __float2bfloat16(t.y - __bfloat162float(h1))),
                pack_bf16(__float2bfloat16(t.z - __bfloat162float(h2)),
                          __float2bfloat16(t.w - __bfloat162float(h3))));
            int off = (r * KP + c4) * 2;
            *(uint2*)(smc + XB(buf) + off)         = hh;
            *(uint2*)(smc + XB(buf) + 18432 + off) = ll;
        }
    };
    auto cpw = [&](int kc, int buf) {
        #pragma unroll
        for (int j = 0; j < 12; ++j) {
            int half = (j >= 6) ? 1 : 0;
            int rem  = tid + (j - 6 * half) * 256;   // 0..1535
            int nab  = rem >> 3;                     // 0..191 = mat*64+n
            int c8   = rem & 7;
            const __nv_bfloat16* src = (half ? g_Wl : g_Wh)
                                     + (size_t)nab * C_ + kc + c8 * 8;
            uint32_t dst = sb + WB(buf) + half * 27648 + nab * 144 + c8 * 16;
            CP16(dst, src);
        }
        CP_COMMIT();
    };

    // prologue
    ldg_x(0);
    cpw(0, 0);

    #pragma unroll 1
    for (int c = 0; c < 16; ++c) {
        const int buf = c & 1;
        if (c < 15) cpw((c + 1) * 64, buf ^ 1);
        cvt_x(buf);
        if (c < 15) ldg_x((c + 1) * 64);
        if (c < 15) asm volatile("cp.async.wait_group 1;" ::: "memory");
        else        asm volatile("cp.async.wait_group 0;" ::: "memory");
        __syncthreads();

        const uint32_t xa = sb + XB(buf) + a_off;
        #pragma unroll
        for (int ks = 0; ks < 4; ++ks) {
            uint32_t ah0, ah1, ah2, ah3, al0, al1, al2, al3;
            ldsm4(ah0, ah1, ah2, ah3, xa + ks * 32);
            ldsm4(al0, al1, al2, al3, xa + 18432 + ks * 32);
            #pragma unroll
            for (int mat = 0; mat < 3; ++mat) {
                #pragma unroll
                for (int nb2 = 0; nb2 < 4; ++nb2) {
                    uint32_t wa = sb + WB(buf) + (mat * 64 + nb2 * 16) * 144
                                + ks * 32 + b_off;
                    uint32_t bh0, bh1, bh2, bh3, bl0, bl1, bl2, bl3;
                    ldsm4(bh0, bh1, bh2, bh3, wa);
                    ldsm4(bl0, bl1, bl2, bl3, wa + 27648);
                    mma16816(acc[mat][nb2 * 2],     ah0, ah1, ah2, ah3, bh0, bh1);
                    mma16816(acc[mat][nb2 * 2],     ah0, ah1, ah2, ah3, bl0, bl1);
                    mma16816(acc[mat][nb2 * 2],     al0, al1, al2, al3, bh0, bh1);
                    mma16816(acc[mat][nb2 * 2 + 1], ah0, ah1, ah2, ah3, bh2, bh3);
                    mma16816(acc[mat][nb2 * 2 + 1], ah0, ah1, ah2, ah3, bl2, bl3);
                    mma16816(acc[mat][nb2 * 2 + 1], al0, al1, al2, al3, bh2, bh3);
                }
            }
        }
        __syncthreads();
    }

    // --- epilogue: add bias, (Q: fold softmax scale), split hi/lo, store bf16 ---
    const int g  = lane >> 2;
    const int tg = lane & 3;
    const int row = m0 + wid * 16 + g;
    #pragma unroll
    for (int mat = 0; mat < 3; ++mat) {
        const float* bias = (mat == 0) ? bq : (mat == 1) ? bk : bv;
        __nv_bfloat16* dh = (mat == 0) ? g_Qh : (mat == 1) ? g_Kh : g_Vh;
        __nv_bfloat16* dl = (mat == 0) ? g_Ql : (mat == 1) ? g_Kl : g_Vl;
        const float scl = (mat == 0) ? 0.03125f : 1.0f;
        #pragma unroll
        for (int nb = 0; nb < 8; ++nb) {
            int col = nb * 8 + tg * 2;
            float b0 = __ldg(bias + col);
            float b1 = __ldg(bias + col + 1);
            float v0 = (acc[mat][nb][0] + b0) * scl;
            float v1 = (acc[mat][nb][1] + b1) * scl;
            float v2 = (acc[mat][nb][2] + b0) * scl;
            float v3 = (acc[mat][nb][3] + b1) * scl;
            __nv_bfloat16 h0 = __float2bfloat16(v0), h1 = __float2bfloat16(v1);
            __nv_bfloat16 h2 = __float2bfloat16(v2), h3 = __float2bfloat16(v3);
            size_t o0 = (size_t)row * H_ + col;
            size_t o1 = (size_t)(row + 8) * H_ + col;
            *(uint32_t*)(dh + o0) = pack_bf16(h0, h1);
            *(uint32_t*)(dh + o1) = pack_bf16(h2, h3);
            *(uint32_t*)(dl + o0) = pack_bf16(
                __float2bfloat16(v0 - __bfloat162float(h0)),
                __float2bfloat16(v1 - __bfloat162float(h1)));
            *(uint32_t*)(dl + o1) = pack_bf16(
                __float2bfloat16(v2 - __bfloat162float(h2)),
                __float2bfloat16(v3 - __bfloat162float(h3)));
        }
    }
}

// ---------------------------------------------------------------------------
// HMMA flash attention, 8 warps: warps 0-3 even k-tiles, 4-7 odd k-tiles,
// private online-softmax state merged at the end. 4-deep cp.async tile ring.
// Pair (qt, 31-qt) per CTA -> 33 tiles, ~17 per warp group. grid (16, 8).
// ---------------------------------------------------------------------------
#define KVROW 144
#define ARR_B (64 * KVROW)        // 9216
#define TILE_B (4 * ARR_B)        // 36864: Kh,Kl,Vh,Vl
#define ATTN_SMEM (4 * TILE_B)    // 147456

__global__ __launch_bounds__(256) void attn_mma(float* __restrict__ out)
{
    extern __shared__ __align__(16) char smk[];
    const uint32_t sb = smem_u32(smk);
    float* msm = (float*)smk;          // merge region (reuses tile buffer 0)
    const int tid  = threadIdx.x;
    const int lane = tid & 31;
    const int wid  = tid >> 5;
    const int wgrp = wid >> 2;         // 0: even tiles, 1: odd tiles
    const int wq4  = wid & 3;          // row group within q-tile
    const int b    = blockIdx.y;
    const int px   = blockIdx.x;
    const int g    = lane >> 2;
    const int tg   = lane & 3;
    const int l8   = lane & 7;
    const int bgrp = lane >> 3;
    const int k_row = ((bgrp & 2) ? 8 : 0) + l8;
    const int k_col = (bgrp & 1) * 16;
    const int v_row = ((bgrp & 1) ? 8 : 0) + l8;
    const int v_col = (bgrp & 2) ? 16 : 0;
    const int bt0   = b * T_;

    #pragma unroll 1
    for (int half = 0; half < 2; ++half) {
        const int qt = half ? (31 - px) : px;
        const int q0 = qt * 64;
        const int nk = qt + 1;

        __syncthreads();   // previous half's smem reads done before reuse

        // ---- Q fragments (registers, hi/lo), rows wq4*16..+15 ----
        uint32_t qh[4][4], ql[4][4];
        {
            const uint32_t* qhp = (const uint32_t*)g_Qh + (size_t)(bt0 + q0 + wq4 * 16) * 32;
            const uint32_t* qlp = (const uint32_t*)g_Ql + (size_t)(bt0 + q0 + wq4 * 16) * 32;
            #pragma unroll
            for (int ks = 0; ks < 4; ++ks) {
                int i0 = g * 32 + ks * 8 + tg;
                int i1 = (g + 8) * 32 + ks * 8 + tg;
                qh[ks][0] = qhp[i0];     qh[ks][1] = qhp[i1];
                qh[ks][2] = qhp[i0 + 4]; qh[ks][3] = qhp[i1 + 4];
                ql[ks][0] = qlp[i0];     ql[ks][1] = qlp[i1];
                ql[ks][2] = qlp[i0 + 4]; ql[ks][3] = qlp[i1 + 4];
            }
        }

        float m0 = -INFINITY, m1 = -INFINITY, l0 = 0.f, l1 = 0.f;
        float o[8][4];
        #pragma unroll
        for (int nb = 0; nb < 8; ++nb)
            o[nb][0] = o[nb][1] = o[nb][2] = o[nb][3] = 0.f;

        auto issue_tile = [&](int vt) {
            if (vt < nk) {
                uint32_t db = sb + (vt & 3) * TILE_B;
                size_t r0 = (size_t)(bt0 + vt * 64);
                #pragma unroll
                for (int j = 0; j < 8; ++j) {
                    int rem = tid + j * 256;      // 0..2047
                    int arr = rem >> 9;
                    int idx = rem & 511;
                    int row = idx >> 3;
                    int c8  = idx & 7;
                    const __nv_bfloat16* sp = (arr == 0) ? g_Kh : (arr == 1) ? g_Kl
                                            : (arr == 2) ? g_Vh : g_Vl;
                    CP16(db + arr * ARR_B + row * KVROW + c8 * 16,
                         sp + (r0 + row) * 64 + c8 * 8);
                }
            }
            CP_COMMIT();
        };

        issue_tile(0); issue_tile(1); issue_tile(2); issue_tile(3);

        const int iters = (nk + 1) >> 1;
        #pragma unroll 1
        for (int it = 0; it < iters; ++it) {
            asm volatile("cp.async.wait_group 2;" ::: "memory");
            __syncthreads();

            const int myt = 2 * it + wgrp;
            if (myt < nk) {
                const uint32_t kb_s = sb + (myt & 3) * TILE_B;
                const uint32_t kv_s = kb_s + 2 * ARR_B;

                // ---- S = Q.K^T (hi/lo split) ----
                float s[8][4];
                #pragma unroll
                for (int nb = 0; nb < 8; ++nb)
                    s[nb][0] = s[nb][1] = s[nb][2] = s[nb][3] = 0.f;

                #pragma unroll
                for (int ks = 0; ks < 4; ++ks) {
                    #pragma unroll
                    for (int np = 0; np < 4; ++np) {
                        uint32_t aH = kb_s + (np * 16 + k_row) * KVROW + k_col + ks * 32;
                        uint32_t bh0, bh1, bh2, bh3, bl0, bl1, bl2, bl3;
                        ldsm4(bh0, bh1, bh2, bh3, aH);
                        ldsm4(bl0, bl1, bl2, bl3, aH + ARR_B);
                        mma16816(s[np * 2],     qh[ks][0], qh[ks][1], qh[ks][2], qh[ks][3], bh0, bh1);
                        mma16816(s[np * 2],     qh[ks][0], qh[ks][1], qh[ks][2], qh[ks][3], bl0, bl1);
                        mma16816(s[np * 2],     ql[ks][0], ql[ks][1], ql[ks][2], ql[ks][3], bh0, bh1);
                        mma16816(s[np * 2 + 1], qh[ks][0], qh[ks][1], qh[ks][2], qh[ks][3], bh2, bh3);
                        mma16816(s[np * 2 + 1], qh[ks][0], qh[ks][1], qh[ks][2], qh[ks][3], bl2, bl3);
                        mma16816(s[np * 2 + 1], ql[ks][0], ql[ks][1], ql[ks][2], ql[ks][3], bh2, bh3);
                    }
                }

                if (myt == qt) {   // causal mask on diagonal tile
                    const int r0 = wq4 * 16 + g;
                    const int r1 = r0 + 8;
                    #pragma unroll
                    for (int nb = 0; nb < 8; ++nb) {
                        int c0 = nb * 8 + tg * 2;
                        if (c0     > r0) s[nb][0] = -INFINITY;
                        if (c0 + 1 > r0) s[nb][1] = -INFINITY;
                        if (c0     > r1) s[nb][2] = -INFINITY;
                        if (c0 + 1 > r1) s[nb][3] = -INFINITY;
                    }
                }

                // ---- online softmax (fp32) ----
                float rm0 = -INFINITY, rm1 = -INFINITY;
                #pragma unroll
                for (int nb = 0; nb < 8; ++nb) {
                    rm0 = fmaxf(rm0, fmaxf(s[nb][0], s[nb][1]));
                    rm1 = fmaxf(rm1, fmaxf(s[nb][2], s[nb][3]));
                }
                rm0 = fmaxf(rm0, __shfl_xor_sync(0xffffffffu, rm0, 1));
                rm0 = fmaxf(rm0, __shfl_xor_sync(0xffffffffu, rm0, 2));
                rm1 = fmaxf(rm1, __shfl_xor_sync(0xffffffffu, rm1, 1));
                rm1 = fmaxf(rm1, __shfl_xor_sync(0xffffffffu, rm1, 2));
                float mn0 = fmaxf(m0, rm0), mn1 = fmaxf(m1, rm1);
                float al0 = __expf(m0 - mn0), al1 = __expf(m1 - mn1);
                float rs0 = 0.f, rs1 = 0.f;
                #pragma unroll
                for (int nb = 0; nb < 8; ++nb) {
                    s[nb][0] = __expf(s[nb][0] - mn0);
                    s[nb][1] = __expf(s[nb][1] - mn0);
                    s[nb][2] = __expf(s[nb][2] - mn1);
                    s[nb][3] = __expf(s[nb][3] - mn1);
                    rs0 += s[nb][0] + s[nb][1];
                    rs1 += s[nb][2] + s[nb][3];
                }
                rs0 += __shfl_xor_sync(0xffffffffu, rs0, 1);
                rs0 += __shfl_xor_sync(0xffffffffu, rs0, 2);
                rs1 += __shfl_xor_sync(0xffffffffu, rs1, 1);
                rs1 += __shfl_xor_sync(0xffffffffu, rs1, 2);
                l0 = l0 * al0 + rs0; m0 = mn0;
                l1 = l1 * al1 + rs1; m1 = mn1;
                #pragma unroll
                for (int nb = 0; nb < 8; ++nb) {
                    o[nb][0] *= al0; o[nb][1] *= al0;
                    o[nb][2] *= al1; o[nb][3] *= al1;
                }

                // ---- O += P.V (P in registers, hi/lo split) ----
                #pragma unroll
                for (int ks = 0; ks < 4; ++ks) {
                    float p00 = s[2 * ks][0],     p01 = s[2 * ks][1];
                    float p02 = s[2 * ks][2],     p03 = s[2 * ks][3];
                    float p10 = s[2 * ks + 1][0], p11 = s[2 * ks + 1][1];
                    float p12 = s[2 * ks + 1][2], p13 = s[2 * ks + 1][3];
                    uint32_t pah0 = pk2(p00, p01), pah1 = pk2(p02, p03);
                    uint32_t pah2 = pk2(p10, p11), pah3 = pk2(p12, p13);
                    uint32_t pal0 = pk2(p00 - bfround(p00), p01 - bfround(p01));
                    uint32_t pal1 = pk2(p02 - bfround(p02), p03 - bfround(p03));
                    uint32_t pal2 = pk2(p10 - bfround(p10), p11 - bfround(p11));
                    uint32_t pal3 = pk2(p12 - bfround(p12), p13 - bfround(p13));
                    #pragma unroll
                    for (int hp = 0; hp < 4; ++hp) {
                        uint32_t aV = kv_s + (ks * 16 + v_row) * KVROW + v_col + hp * 32;
                        uint32_t vh0, vh1, vh2, vh3, vl0, vl1, vl2, vl3;
                        ldsm4t(vh0, vh1, vh2, vh3, aV);
                        ldsm4t(vl0, vl1, vl2, vl3, aV + ARR_B);
                        mma16816(o[hp * 2],     pah0, pah1, pah2, pah3, vh0, vh1);
                        mma16816(o[hp * 2],     pah0, pah1, pah2, pah3, vl0, vl1);
                        mma16816(o[hp * 2],     pal0, pal1, pal2, pal3, vh0, vh1);
                        mma16816(o[hp * 2 + 1], pah0, pah1, pah2, pah3, vh2, vh3);
                        mma16816(o[hp * 2 + 1], pah0, pah1, pah2, pah3, vl2, vl3);
                        mma16816(o[hp * 2 + 1], pal0, pal1, pal2, pal3, vh2, vh3);
                    }
                }
            }
            __syncthreads();
            issue_tile(2 * it + 4);
            issue_tile(2 * it + 5);
        }

        // ---- merge group 1 into group 0, then epilogue by group 0 ----
        if (wgrp == 1) {
            float* p = msm + ((size_t)(wq4 * 32 + lane)) * 36;
            #pragma unroll
            for (int nb = 0; nb < 8; ++nb) {
                p[nb * 4 + 0] = o[nb][0]; p[nb * 4 + 1] = o[nb][1];
                p[nb * 4 + 2] = o[nb][2]; p[nb * 4 + 3] = o[nb][3];
            }
            p[32] = m0; p[33] = l0; p[34] = m1; p[35] = l1;
        }
        __syncthreads();
        if (wgrp == 0) {
            const float* p = msm + ((size_t)(wq4 * 32 + lane)) * 36;
            float om0 = p[32], ol0 = p[33], om1 = p[34], ol1 = p[35];
            float M0 = fmaxf(m0, om0), M1 = fmaxf(m1, om1);
            float A0 = __expf(m0 - M0), B0 = __expf(om0 - M0);
            float A1 = __expf(m1 - M1), B1 = __expf(om1 - M1);
            float inv0 = 1.0f / (l0 * A0 + ol0 * B0);
            float inv1 = 1.0f / (l1 * A1 + ol1 * B1);
            float* orow0 = out + (size_t)(bt0 + q0 + wq4 * 16 + g) * H_;
            float* orow1 = orow0 + 8 * H_;
            #pragma unroll
            for (int nb = 0; nb < 8; ++nb) {
                int col = nb * 8 + tg * 2;
                float e0 = (o[nb][0] * A0 + p[nb * 4 + 0] * B0) * inv0;
                float e1 = (o[nb][1] * A0 + p[nb * 4 + 1] * B0) * inv0;
                float e2 = (o[nb][2] * A1 + p[nb * 4 + 2] * B1) * inv1;
                float e3 = (o[nb][3] * A1 + p[nb * 4 + 3] * B1) * inv1;
                *(float2*)(orow0 + col) = make_float2(e0, e1);
                *(float2*)(orow1 + col) = make_float2(e2, e3);
            }
        }
    }
}

// ---------------------------------------------------------------------------
extern "C" void kernel_launch(void* const* d_in, const int* in_sizes, int n_in,
                              void* d_out, int out_size)
{
    const float* x  = (const float*)d_in[0];
    const float* wq = (const float*)d_in[1];
    const float* bq = (const float*)d_in[2];
    const float* wk = (const float*)d_in[3];
    const float* bk = (const float*)d_in[4];
    const float* wv = (const float*)d_in[5];
    const float* bv = (const float*)d_in[6];
    float* out = (float*)d_out;

    prep_w<<<(3 * H_ * C_ + 255) / 256, 256>>>(wq, wk, wv);

    cudaFuncSetAttribute(proj_mma, cudaFuncAttributeMaxDynamicSharedMemorySize, PROJ_SMEM);
    proj_mma<<<128, 256, PROJ_SMEM>>>(x, bq, bk, bv);

    cudaFuncSetAttribute(attn_mma, cudaFuncAttributeMaxDynamicSharedMemorySize, ATTN_SMEM);
    attn_mma<<<dim3(16, 8), 256, ATTN_SMEM>>>(out);
}